// round 5
// baseline (speedup 1.0000x reference)
#include <cuda_runtime.h>
#include <cuda_bf16.h>
#include <cstdint>

// Problem constants
#define Bn  16
#define Cc  256
#define HWc 4096
#define Nq  65536
#define Kc  1024
#define ZQ_ELEMS 16777216

#define FLAG_THRESH 3e-4f
#define FINF __int_as_float(0x7f800000)

// -------------------------- device scratch --------------------------------
__device__ float g_cbT[Cc * Kc];              // codebook transposed [C][K] (write_zq)
__device__ float g_bnorm[Kc];                 // ||c_k||^2 (same chain as R1)
__device__ __nv_bfloat16 g_cbh[Kc * Cc];      // codebook hi split  [k][c]
__device__ __nv_bfloat16 g_cbm[Kc * Cc];      // codebook mid split [k][c]
__device__ int   g_idx[Nq];
__device__ float g_dbest[Nq];
__device__ int   g_fix_count;
__device__ int   g_fix_list[Nq];

// -------------------------- helpers ---------------------------------------
__device__ __forceinline__ uint32_t smem_u32(const void* p) {
    uint32_t a;
    asm("{ .reg .u64 t; cvta.to.shared.u64 t, %1; cvt.u32.u64 %0, t; }" : "=r"(a) : "l"(p));
    return a;
}
__device__ __forceinline__ void ldsm4(uint32_t* r, uint32_t a) {
    asm volatile("ldmatrix.sync.aligned.m8n8.x4.shared.b16 {%0,%1,%2,%3}, [%4];"
                 : "=r"(r[0]), "=r"(r[1]), "=r"(r[2]), "=r"(r[3]) : "r"(a));
}
__device__ __forceinline__ void mma16816(float* d, const uint32_t* a,
                                         uint32_t b0, uint32_t b1) {
    asm volatile("mma.sync.aligned.m16n8k16.row.col.f32.bf16.bf16.f32 "
                 "{%0,%1,%2,%3}, {%4,%5,%6,%7}, {%8,%9}, {%0,%1,%2,%3};"
                 : "+f"(d[0]), "+f"(d[1]), "+f"(d[2]), "+f"(d[3])
                 : "r"(a[0]), "r"(a[1]), "r"(a[2]), "r"(a[3]), "r"(b0), "r"(b1));
}

// -------------------------- smem layout (bytes) ----------------------------
// A tiles: 128 q x 256 c bf16, row stride 512B, granule swizzle kg ^= (row&7)
#define OFF_AS   0          // float As[128]
#define OFF_EM1  512        // float em1[128]
#define OFF_EM2  1024       // float em2[128]
#define OFF_EI1  1536       // int   ei1[128]
#define OFF_A0   2048       // 65536 (hi split)
#define OFF_A1   67584      // 65536 (mid split)
#define OFF_B0   133120     // 32768 (64 codes x 256 c, hi)
#define OFF_B1   165888     // 32768 (mid)
#define OFF_Z    198656     // 32768 fp32 temp [64 c][128 q]
#define SMEM_BYTES 231424

// ---------------------------------------------------------------------------
// Prep: cbT + bnorm (identical chain to R1) + bf16 splits + counter reset
// ---------------------------------------------------------------------------
__global__ void prep_kernel(const float* __restrict__ cb) {
    int k = blockIdx.x, c = threadIdx.x;
    float v = cb[k * Cc + c];
    g_cbT[c * Kc + k] = v;
    __nv_bfloat16 h = __float2bfloat16_rn(v);
    float r = v - __bfloat162float(h);
    __nv_bfloat16 m = __float2bfloat16_rn(r);
    g_cbh[k * Cc + c] = h;
    g_cbm[k * Cc + c] = m;
    __shared__ float sred[256];
    sred[c] = v * v;
    __syncthreads();
    for (int s = 128; s > 0; s >>= 1) {
        if (c < s) sred[c] += sred[c + s];
        __syncthreads();
    }
    if (c == 0) {
        g_bnorm[k] = sred[0];
        if (k == 0) g_fix_count = 0;
    }
}

// ---------------------------------------------------------------------------
// Main HMMA kernel: 512 CTAs x 256 threads (8 warps).
// Per CTA: 128 queries vs all 1024 codes. A (bf16 hi/mid) resident in smem;
// B streamed in 64-code chunks; 3 split passes (hh, hm, mh) into fp32 accum.
// ---------------------------------------------------------------------------
__global__ void __launch_bounds__(256) vq_hmma(const float* __restrict__ z) {
    extern __shared__ char smem[];
    const uint32_t sb = smem_u32(smem);
    float* As   = (float*)(smem + OFF_AS);
    float* em1  = (float*)(smem + OFF_EM1);
    float* em2  = (float*)(smem + OFF_EM2);
    int*   ei1  = (int*)(smem + OFF_EI1);
    float* zbuf = (float*)(smem + OFF_Z);

    const int tid  = threadIdx.x;
    const int lane = tid & 31, w = tid >> 5;
    const int n0 = blockIdx.x * 128;
    const float* zb = z + (size_t)(n0 >> 12) * (Cc * HWc) + (n0 & (HWc - 1));

    // ---------------- stage A: load z, norms, bf16 split+swizzle ----------
    float anorm = 0.f;
    for (int cc = 0; cc < 4; ++cc) {
        __syncthreads();          // zbuf free (prev conversion done)
        #pragma unroll
        for (int i = 0; i < 8; ++i) {
            int f = tid + 256 * i; int r = f >> 5, q4 = f & 31;
            ((float4*)zbuf)[r * 32 + q4] =
                ((const float4*)(zb + (size_t)(cc * 64 + r) * HWc))[q4];
        }
        __syncthreads();

        // norms: sequential fmaf over c ascending (exact R1 chain)
        if (tid < 128) {
            #pragma unroll 8
            for (int r = 0; r < 64; ++r) {
                float v = zbuf[r * 128 + tid];
                anorm = fmaf(v, v, anorm);
            }
            if (cc == 3) As[tid] = anorm;
        }

        // convert: q = tid&127 handles 64 c values (two 16B granule pairs x2)
        {
            int q = tid & 127, half2 = tid >> 7;
            #pragma unroll
            for (int g2 = 0; g2 < 2; ++g2) {
                int c0 = (half2 * 2 + g2) * 16;      // local c base (0..48)
                uint32_t hp[8], mp[8];
                #pragma unroll
                for (int j = 0; j < 8; ++j) {
                    float v0 = zbuf[(c0 + 2 * j) * 128 + q];
                    float v1 = zbuf[(c0 + 2 * j + 1) * 128 + q];
                    __nv_bfloat16 h0 = __float2bfloat16_rn(v0);
                    __nv_bfloat16 h1 = __float2bfloat16_rn(v1);
                    float r0 = v0 - __bfloat162float(h0);
                    float r1 = v1 - __bfloat162float(h1);
                    __nv_bfloat16 m0 = __float2bfloat16_rn(r0);
                    __nv_bfloat16 m1 = __float2bfloat16_rn(r1);
                    hp[j] = (uint32_t)__bfloat16_as_ushort(h0) |
                            ((uint32_t)__bfloat16_as_ushort(h1) << 16);
                    mp[j] = (uint32_t)__bfloat16_as_ushort(m0) |
                            ((uint32_t)__bfloat16_as_ushort(m1) << 16);
                }
                int kg = cc * 8 + (c0 >> 3);         // 16B granule index (0..31)
                uint32_t d0 = (uint32_t)q * 512 + (((kg ^ (q & 7)) & 31) << 4);
                uint32_t d1 = (uint32_t)q * 512 + ((((kg + 1) ^ (q & 7)) & 31) << 4);
                *(uint4*)(smem + OFF_A0 + d0) = make_uint4(hp[0], hp[1], hp[2], hp[3]);
                *(uint4*)(smem + OFF_A0 + d1) = make_uint4(hp[4], hp[5], hp[6], hp[7]);
                *(uint4*)(smem + OFF_A1 + d0) = make_uint4(mp[0], mp[1], mp[2], mp[3]);
                *(uint4*)(smem + OFF_A1 + d1) = make_uint4(mp[4], mp[5], mp[6], mp[7]);
            }
        }
    }
    __syncthreads();

    // ---------------- warp/lane geometry -----------------------------------
    const int warp_m = (w & 3) * 32;       // query tile base (4 warps along m)
    const int warp_n = (w >> 2) * 32;      // code column half within 64-chunk
    const int g = lane >> 2, t4 = lane & 3;
    const int lA = lane & 15, hA = lane >> 4;
    const uint32_t swA = (uint32_t)(lA & 7) << 4;
    const uint32_t rbA0 = (uint32_t)(warp_m + lA) * 512;
    const uint32_t rbA1 = (uint32_t)(warp_m + 16 + lA) * 512;
    const uint32_t rbB0 = (uint32_t)(warp_n + lA) * 512;
    const uint32_t rbB1 = (uint32_t)(warp_n + 16 + lA) * 512;

    float lm1[4], lm2[4]; int li[4];
    #pragma unroll
    for (int s = 0; s < 4; ++s) { lm1[s] = FINF; lm2[s] = FINF; li[s] = 0; }

    // ---------------- main loop over 16 B-chunks of 64 codes ---------------
    for (int nch = 0; nch < 16; ++nch) {
        const int kb = nch * 64;
        // stage B chunk (both splits), swizzled
        #pragma unroll
        for (int i = 0; i < 8; ++i) {
            int idx = tid + 256 * i;                 // 0..2047
            int r = idx >> 5, kg = idx & 31;
            size_t gi = (size_t)(kb + r) * Cc + (size_t)kg * 8;
            uint32_t dst = (uint32_t)r * 512 + (((kg ^ (r & 7)) & 31) << 4);
            *(uint4*)(smem + OFF_B0 + dst) = *(const uint4*)(g_cbh + gi);
            *(uint4*)(smem + OFF_B1 + dst) = *(const uint4*)(g_cbm + gi);
        }
        __syncthreads();

        float acc[2][4][4];
        #pragma unroll
        for (int i = 0; i < 2; ++i)
            #pragma unroll
            for (int j = 0; j < 4; ++j)
                #pragma unroll
                for (int e = 0; e < 4; ++e) acc[i][j][e] = 0.f;

        #pragma unroll 1
        for (int p = 0; p < 3; ++p) {                // hh, hm, mh
            const uint32_t Ab = sb + (p == 2 ? OFF_A1 : OFF_A0);
            const uint32_t Bb = sb + (p == 1 ? OFF_B1 : OFF_B0);
            #pragma unroll 4
            for (int ks = 0; ks < 16; ++ks) {
                uint32_t offA = ((((uint32_t)(2 * ks + hA)) << 4) ^ swA);
                uint32_t a0[4], a1[4], bq0[4], bq1[4];
                ldsm4(a0,  Ab + rbA0 + offA);
                ldsm4(a1,  Ab + rbA1 + offA);
                ldsm4(bq0, Bb + rbB0 + offA);
                ldsm4(bq1, Bb + rbB1 + offA);
                mma16816(acc[0][0], a0, bq0[0], bq0[2]);
                mma16816(acc[0][1], a0, bq0[1], bq0[3]);
                mma16816(acc[0][2], a0, bq1[0], bq1[2]);
                mma16816(acc[0][3], a0, bq1[1], bq1[3]);
                mma16816(acc[1][0], a1, bq0[0], bq0[2]);
                mma16816(acc[1][1], a1, bq0[1], bq0[3]);
                mma16816(acc[1][2], a1, bq1[0], bq1[2]);
                mma16816(acc[1][3], a1, bq1[1], bq1[3]);
            }
        }

        // epilogue: distances + running min1/min2 (k ascending within lane)
        #pragma unroll
        for (int i = 0; i < 2; ++i)
            #pragma unroll
            for (int rp = 0; rp < 2; ++rp) {
                int s = i * 2 + rp;
                float Aq = As[warp_m + 16 * i + 8 * rp + g];
                #pragma unroll
                for (int j = 0; j < 4; ++j)
                    #pragma unroll
                    for (int e = 0; e < 2; ++e) {
                        int k = kb + warp_n + 8 * j + 2 * t4 + e;
                        float d = fmaf(-2.f, acc[i][j][rp * 2 + e],
                                       __fadd_rn(Aq, g_bnorm[k]));
                        if (d < lm1[s]) { lm2[s] = lm1[s]; lm1[s] = d; li[s] = k; }
                        else if (d < lm2[s]) { lm2[s] = d; }
                    }
            }
        __syncthreads();   // before next chunk overwrites B
    }

    // ---------------- reduce: quad lanes -> cross-warp -> global -----------
    #pragma unroll
    for (int s = 0; s < 4; ++s) {
        #pragma unroll
        for (int off = 1; off <= 2; off <<= 1) {
            float om1 = __shfl_xor_sync(0xffffffffu, lm1[s], off);
            float om2 = __shfl_xor_sync(0xffffffffu, lm2[s], off);
            int   oi  = __shfl_xor_sync(0xffffffffu, li[s], off);
            float nm2 = fminf(fminf(lm2[s], om2), fmaxf(lm1[s], om1));
            if (om1 < lm1[s] || (om1 == lm1[s] && oi < li[s])) { lm1[s] = om1; li[s] = oi; }
            lm2[s] = nm2;
        }
    }
    if (warp_n == 32 && t4 == 0) {
        #pragma unroll
        for (int s = 0; s < 4; ++s) {
            int row = warp_m + 16 * (s >> 1) + 8 * (s & 1) + g;
            em1[row] = lm1[s]; em2[row] = lm2[s]; ei1[row] = li[s];
        }
    }
    __syncthreads();
    if (warp_n == 0 && t4 == 0) {
        #pragma unroll
        for (int s = 0; s < 4; ++s) {
            int row = warp_m + 16 * (s >> 1) + 8 * (s & 1) + g;
            float pm1 = em1[row], pm2 = em2[row]; int pi1 = ei1[row];
            float M2 = fminf(fminf(lm2[s], pm2), fmaxf(lm1[s], pm1));
            float M1 = lm1[s]; int I1 = li[s];
            if (pm1 < M1 || (pm1 == M1 && pi1 < I1)) { M1 = pm1; I1 = pi1; }
            int q = n0 + row;
            g_idx[q] = I1;
            g_dbest[q] = M1;
            if (M2 - M1 <= FLAG_THRESH) {
                int sl = atomicAdd(&g_fix_count, 1);
                g_fix_list[sl] = q;
            }
        }
    }
}

// ---------------------------------------------------------------------------
// Fixup: exact fp32 recompute (R1 chain, proven rel_err 0.0) for near-ties.
// ---------------------------------------------------------------------------
__global__ void fixup_kernel(const float* __restrict__ z, const float* __restrict__ cb) {
    __shared__ float zq[256];
    __shared__ float rm[256];
    __shared__ int   rk[256];
    int cnt = g_fix_count;
    for (int it = blockIdx.x; it < cnt; it += gridDim.x) {
        int q = g_fix_list[it];
        int b = q >> 12, hw = q & 4095;
        zq[threadIdx.x] = z[((size_t)(b * 256 + threadIdx.x)) * 4096 + hw];
        __syncthreads();
        float A = 0.f;
        #pragma unroll 8
        for (int c = 0; c < 256; ++c) A = fmaf(zq[c], zq[c], A);
        float bm = FINF; int bk = 0;
        for (int t = 0; t < 4; ++t) {
            int k = threadIdx.x + 256 * t;
            const float* cr = cb + (size_t)k * 256;
            float dot = 0.f;
            #pragma unroll 8
            for (int c = 0; c < 256; ++c) dot = fmaf(zq[c], cr[c], dot);
            float d = fmaf(-2.f, dot, __fadd_rn(A, g_bnorm[k]));
            if (d < bm) { bm = d; bk = k; }
        }
        rm[threadIdx.x] = bm; rk[threadIdx.x] = bk;
        __syncthreads();
        for (int s = 128; s > 0; s >>= 1) {
            if (threadIdx.x < s) {
                float v = rm[threadIdx.x + s]; int kk = rk[threadIdx.x + s];
                if (v < rm[threadIdx.x] ||
                    (v == rm[threadIdx.x] && kk < rk[threadIdx.x])) {
                    rm[threadIdx.x] = v; rk[threadIdx.x] = kk;
                }
            }
            __syncthreads();
        }
        if (threadIdx.x == 0) { g_idx[q] = rk[0]; g_dbest[q] = rm[0]; }
        __syncthreads();
    }
}

// ---------------------------------------------------------------------------
__global__ void write_zq(float* __restrict__ out, const float* __restrict__ z) {
    int p = blockIdx.x;               // b*256 + c
    int b = p >> 8, c = p & 255;
    const float* row  = g_cbT + (size_t)c * Kc;
    const int*   idxp = g_idx + b * HWc;
    const float* zp   = z + (size_t)p * HWc;
    float*       o    = out + (size_t)p * HWc;
    for (int hw = threadIdx.x; hw < HWc; hw += blockDim.x) {
        float zc = zp[hw];
        float zqv = row[idxp[hw]];
        o[hw] = __fadd_rn(zc, __fsub_rn(zqv, zc));
    }
}

__global__ void write_idx(float* __restrict__ out) {
    int n = blockIdx.x * blockDim.x + threadIdx.x;
    if (n < Nq) out[n] = (float)g_idx[n];
}

__global__ void loss_kernel(float* __restrict__ out) {
    __shared__ double sd[256];
    double s = 0.0;
    for (int i = threadIdx.x; i < Nq; i += 256) s += (double)g_dbest[i];
    sd[threadIdx.x] = s;
    __syncthreads();
    for (int r = 128; r > 0; r >>= 1) {
        if (threadIdx.x < r) sd[threadIdx.x] += sd[threadIdx.x + r];
        __syncthreads();
    }
    if (threadIdx.x == 0)
        out[0] = (float)(0.75 * sd[0] / (double)ZQ_ELEMS);
}

// ---------------------------------------------------------------------------
extern "C" void kernel_launch(void* const* d_in, const int* in_sizes, int n_in,
                              void* d_out, int out_size) {
    const float* z  = (const float*)d_in[0];   // [B,C,H,W] fp32
    const float* cb = (const float*)d_in[1];   // [K,C]     fp32
    float* out = (float*)d_out;

    cudaFuncSetAttribute(vq_hmma, cudaFuncAttributeMaxDynamicSharedMemorySize, SMEM_BYTES);

    prep_kernel<<<Kc, 256>>>(cb);
    vq_hmma<<<Nq / 128, 256, SMEM_BYTES>>>(z);
    fixup_kernel<<<4096, 256>>>(z, cb);
    write_zq<<<Bn * Cc, 256>>>(out, z);

    if (out_size >= ZQ_ELEMS + Nq)
        write_idx<<<Nq / 256, 256>>>(out + ZQ_ELEMS);
    if (out_size >= ZQ_ELEMS + Nq + 1)
        loss_kernel<<<1, 256>>>(out + ZQ_ELEMS + Nq);
    else if (out_size == ZQ_ELEMS + 1)
        loss_kernel<<<1, 256>>>(out + ZQ_ELEMS);
}